// round 11
// baseline (speedup 1.0000x reference)
#include <cuda_runtime.h>
#include <cstdint>

#define NNODES 100000
#define MAXF   300

// Scratch (static __device__ arrays: allocation-guard compliant)
__device__ float g_support[(size_t)NNODES * MAXF];
__device__ float g_agg[(size_t)NNODES * MAXF];

// ---------------------------------------------------------------------------
// packed fp32x2 helpers (Blackwell: fma.rn.f32x2 doubles fp32 FMA throughput)
// ---------------------------------------------------------------------------
__device__ __forceinline__ unsigned long long pk2(float lo, float hi) {
    unsigned long long r;
    asm("mov.b64 %0, {%1, %2};" : "=l"(r) : "f"(lo), "f"(hi));
    return r;
}
__device__ __forceinline__ void fma2(unsigned long long& d,
                                     unsigned long long a,
                                     unsigned long long b) {
    asm("fma.rn.f32x2 %0, %1, %2, %0;" : "+l"(d) : "l"(a), "l"(b));
}
__device__ __forceinline__ void unpk2(unsigned long long v, float& lo, float& hi) {
    asm("mov.b64 {%0, %1}, %2;" : "=f"(lo), "=f"(hi) : "l"(v));
}

// ---------------------------------------------------------------------------
// zero: vectorized grid-stride fill
// ---------------------------------------------------------------------------
__global__ void zero_kernel(float4* __restrict__ p, int n4) {
    for (int i = blockIdx.x * blockDim.x + threadIdx.x; i < n4;
         i += gridDim.x * blockDim.x)
        p[i] = make_float4(0.f, 0.f, 0.f, 0.f);
}

// ---------------------------------------------------------------------------
// GEMM: C[M,N] = f(A)[M,K] @ W[K,N]
//   f(A) = relu(A + prev_bias[k]) when prev_bias != nullptr, else A.
// 256x64x16 tiles, 256 threads, 8x8 register microtile, packed f32x2 FMA.
// Per k: 4 LDS.128 feed 32 FFMA2 (2 B smem per packed FMA).
// ---------------------------------------------------------------------------
__global__ __launch_bounds__(256, 2) void gemm_kernel(
    const float* __restrict__ A, const float* __restrict__ pb,
    const float* __restrict__ W, float* __restrict__ C,
    int M, int K, int N)
{
    const int BM = 256, BN = 64, BK = 16;
    __shared__ float As[BK][BM];   // transposed (k-major)
    __shared__ float Bs[BK][BN];

    int tid = threadIdx.x;
    int tx = tid & 7;      // col group 0..7  (8 cols each)
    int ty = tid >> 3;     // row group 0..31 (8 rows each)
    int rowBase = blockIdx.x * BM;
    int colBase = blockIdx.y * BN;

    // acc[i2][j]: packed rows (ty*8 + 2*i2, +1) x col (tx*8 + j)
    unsigned long long acc[4][8];
#pragma unroll
    for (int i = 0; i < 4; i++)
#pragma unroll
        for (int j = 0; j < 8; j++) acc[i][j] = 0ULL;

    for (int k0 = 0; k0 < K; k0 += BK) {
        // ---- load A tile: 256 rows x 16 k = 1024 float4, 4 per thread ----
#pragma unroll
        for (int it = 0; it < 4; it++) {
            int idx = it * 256 + tid;
            int ar = idx >> 2;        // 0..255
            int aq = idx & 3;         // 0..3 (k-quad)
            int arow = rowBase + ar;
            int ak = k0 + aq * 4;
            float4 av = make_float4(0.f, 0.f, 0.f, 0.f);
            if (arow < M) {
                if (ak + 4 <= K) {
                    av = *(const float4*)(A + (size_t)arow * K + ak);
                    if (pb) {
                        av.x = fmaxf(av.x + __ldg(pb + ak + 0), 0.f);
                        av.y = fmaxf(av.y + __ldg(pb + ak + 1), 0.f);
                        av.z = fmaxf(av.z + __ldg(pb + ak + 2), 0.f);
                        av.w = fmaxf(av.w + __ldg(pb + ak + 3), 0.f);
                    }
                } else {
                    float t[4] = {0.f, 0.f, 0.f, 0.f};
#pragma unroll
                    for (int u = 0; u < 4; u++) {
                        if (ak + u < K) {
                            float v = A[(size_t)arow * K + ak + u];
                            if (pb) v = fmaxf(v + pb[ak + u], 0.f);
                            t[u] = v;
                        }
                    }
                    av = make_float4(t[0], t[1], t[2], t[3]);
                }
            }
            As[aq * 4 + 0][ar] = av.x;
            As[aq * 4 + 1][ar] = av.y;
            As[aq * 4 + 2][ar] = av.z;
            As[aq * 4 + 3][ar] = av.w;
        }

        // ---- load B tile: 16 k-rows x 64 cols = 256 float4, 1 per thread ----
        {
            int br = tid >> 4;        // 0..15 (k-row)
            int bq = tid & 15;        // 0..15 (float4 quad along N)
            int brow = k0 + br;
            int bcol = colBase + bq * 4;
            float4 bv = make_float4(0.f, 0.f, 0.f, 0.f);
            if (brow < K) {
                if (bcol + 4 <= N) {
                    bv = *(const float4*)(W + (size_t)brow * N + bcol);
                } else {
                    float t[4] = {0.f, 0.f, 0.f, 0.f};
#pragma unroll
                    for (int u = 0; u < 4; u++)
                        if (bcol + u < N) t[u] = W[(size_t)brow * N + bcol + u];
                    bv = make_float4(t[0], t[1], t[2], t[3]);
                }
            }
            *(float4*)&Bs[br][bq * 4] = bv;
        }

        __syncthreads();

#pragma unroll
        for (int k = 0; k < BK; k++) {
            float4 a0 = *(const float4*)&As[k][ty * 8];
            float4 a1 = *(const float4*)&As[k][ty * 8 + 4];
            float4 b0 = *(const float4*)&Bs[k][tx * 8];
            float4 b1 = *(const float4*)&Bs[k][tx * 8 + 4];

            unsigned long long ap[4];
            ap[0] = pk2(a0.x, a0.y);
            ap[1] = pk2(a0.z, a0.w);
            ap[2] = pk2(a1.x, a1.y);
            ap[3] = pk2(a1.z, a1.w);

            unsigned long long bp[8];
            bp[0] = pk2(b0.x, b0.x);
            bp[1] = pk2(b0.y, b0.y);
            bp[2] = pk2(b0.z, b0.z);
            bp[3] = pk2(b0.w, b0.w);
            bp[4] = pk2(b1.x, b1.x);
            bp[5] = pk2(b1.y, b1.y);
            bp[6] = pk2(b1.z, b1.z);
            bp[7] = pk2(b1.w, b1.w);

#pragma unroll
            for (int i2 = 0; i2 < 4; i2++)
#pragma unroll
                for (int j = 0; j < 8; j++)
                    fma2(acc[i2][j], ap[i2], bp[j]);
        }
        __syncthreads();
    }

    // ---- store ----
#pragma unroll
    for (int i2 = 0; i2 < 4; i2++) {
        int r0 = rowBase + ty * 8 + i2 * 2;
#pragma unroll
        for (int j = 0; j < 8; j++) {
            int col = colBase + tx * 8 + j;
            if (col >= N) continue;
            float lo, hi;
            unpk2(acc[i2][j], lo, hi);
            if (r0 < M)     C[(size_t)r0 * N + col] = lo;
            if (r0 + 1 < M) C[(size_t)(r0 + 1) * N + col] = hi;
        }
    }
}

// ---------------------------------------------------------------------------
// Edge scatter: agg[dst] += support[src] * w, vectorized float4 + red.global.v4
// ---------------------------------------------------------------------------
template <int F>
__global__ __launch_bounds__(256) void scatter_kernel(
    const float* __restrict__ support,
    const int* __restrict__ src, const int* __restrict__ dst,
    const float* __restrict__ ew,
    float* __restrict__ agg, int E)
{
    constexpr int NCH = F / 4;
    int t = blockIdx.x * blockDim.x + threadIdx.x;
    if (t >= E * NCH) return;
    int e = t / NCH;
    int c = t - e * NCH;

    int s = __ldg(src + e);
    int d = __ldg(dst + e);
    float w = __ldg(ew + e);

    float4 v = __ldg((const float4*)(support + (size_t)s * F) + c);
    v.x *= w; v.y *= w; v.z *= w; v.w *= w;

    float* out = agg + (size_t)d * F + c * 4;
    asm volatile("red.global.add.v4.f32 [%0], {%1, %2, %3, %4};"
                 :: "l"(out), "f"(v.x), "f"(v.y), "f"(v.z), "f"(v.w)
                 : "memory");
}

// ---------------------------------------------------------------------------
// Softmax over 40 classes; one warp per node. input = agg + b3.
// ---------------------------------------------------------------------------
__global__ __launch_bounds__(256) void softmax_kernel(
    const float* __restrict__ agg, const float* __restrict__ b,
    float* __restrict__ out, int M)
{
    int warp = (blockIdx.x * blockDim.x + threadIdx.x) >> 5;
    int lane = threadIdx.x & 31;
    if (warp >= M) return;

    const float* row = agg + (size_t)warp * 40;
    float v0 = row[lane] + __ldg(b + lane);
    float v1 = (lane < 8) ? row[32 + lane] + __ldg(b + 32 + lane) : -3.4e38f;

    float m = fmaxf(v0, v1);
#pragma unroll
    for (int o = 16; o > 0; o >>= 1) m = fmaxf(m, __shfl_xor_sync(0xFFFFFFFFu, m, o));

    float e0 = __expf(v0 - m);
    float e1 = (lane < 8) ? __expf(v1 - m) : 0.f;
    float s = e0 + e1;
#pragma unroll
    for (int o = 16; o > 0; o >>= 1) s += __shfl_xor_sync(0xFFFFFFFFu, s, o);

    float inv = 1.f / s;
    float* orow = out + (size_t)warp * 40;
    orow[lane] = e0 * inv;
    if (lane < 8) orow[32 + lane] = e1 * inv;
}

// ---------------------------------------------------------------------------
// launch
// ---------------------------------------------------------------------------
extern "C" void kernel_launch(void* const* d_in, const int* in_sizes, int n_in,
                              void* d_out, int out_size)
{
    const float* x  = (const float*)d_in[0];
    const int*   ei = (const int*)d_in[1];
    const float* ew = (const float*)d_in[2];
    const float* w1 = (const float*)d_in[3];
    const float* b1 = (const float*)d_in[4];
    const float* w2 = (const float*)d_in[5];
    const float* b2 = (const float*)d_in[6];
    const float* w3 = (const float*)d_in[7];
    const float* b3 = (const float*)d_in[8];
    float* out = (float*)d_out;

    const int M = NNODES;
    const int E = in_sizes[2];
    const int* src = ei;
    const int* dst = ei + E;

    float *support, *agg;
    cudaGetSymbolAddress((void**)&support, g_support);
    cudaGetSymbolAddress((void**)&agg, g_agg);

    // ---- Layer 1: support = x @ w1 ; agg = A @ support ----
    {
        const int K = 512, N = 300;
        dim3 grid((M + 255) / 256, (N + 63) / 64);
        gemm_kernel<<<grid, 256>>>(x, nullptr, w1, support, M, K, N);
        int n4 = M * N / 4;
        zero_kernel<<<2048, 256>>>((float4*)agg, n4);
        long long tot = (long long)E * (N / 4);
        scatter_kernel<300><<<(unsigned)((tot + 255) / 256), 256>>>(
            support, src, dst, ew, agg, E);
    }
    // ---- Layer 2: support = relu(agg + b1) @ w2 ; agg = A @ support ----
    {
        const int K = 300, N = 200;
        dim3 grid((M + 255) / 256, (N + 63) / 64);
        gemm_kernel<<<grid, 256>>>(agg, b1, w2, support, M, K, N);
        int n4 = M * N / 4;
        zero_kernel<<<2048, 256>>>((float4*)agg, n4);
        long long tot = (long long)E * (N / 4);
        scatter_kernel<200><<<(unsigned)((tot + 255) / 256), 256>>>(
            support, src, dst, ew, agg, E);
    }
    // ---- Layer 3: support = relu(agg + b2) @ w3 ; agg = A @ support ----
    {
        const int K = 200, N = 40;
        dim3 grid((M + 255) / 256, (N + 63) / 64);
        gemm_kernel<<<grid, 256>>>(agg, b2, w3, support, M, K, N);
        int n4 = M * N / 4;
        zero_kernel<<<1024, 256>>>((float4*)agg, n4);
        long long tot = (long long)E * (N / 4);
        scatter_kernel<40><<<(unsigned)((tot + 255) / 256), 256>>>(
            support, src, dst, ew, agg, E);
    }
    // ---- softmax(agg + b3) -> out ----
    {
        int warpsPerBlock = 256 / 32;
        int grid = (M + warpsPerBlock - 1) / warpsPerBlock;
        softmax_kernel<<<grid, 256>>>(agg, b3, out, M);
    }
}

// round 15
// speedup vs baseline: 1.2305x; 1.2305x over previous
#include <cuda_runtime.h>
#include <cstdint>

#define NNODES 100000
#define MAXF   300

// Scratch (static __device__ arrays: allocation-guard compliant)
__device__ float g_support[(size_t)NNODES * MAXF];
__device__ float g_agg[(size_t)NNODES * MAXF];

// ---------------------------------------------------------------------------
// packed fp32x2 helpers (Blackwell: fma.rn.f32x2 doubles fp32 FMA throughput)
// ---------------------------------------------------------------------------
__device__ __forceinline__ unsigned long long pk2(float lo, float hi) {
    unsigned long long r;
    asm("mov.b64 %0, {%1, %2};" : "=l"(r) : "f"(lo), "f"(hi));
    return r;
}
__device__ __forceinline__ void fma2(unsigned long long& d,
                                     unsigned long long a,
                                     unsigned long long b) {
    asm("fma.rn.f32x2 %0, %1, %2, %0;" : "+l"(d) : "l"(a), "l"(b));
}
__device__ __forceinline__ void unpk2(unsigned long long v, float& lo, float& hi) {
    asm("mov.b64 {%0, %1}, %2;" : "=f"(lo), "=f"(hi) : "l"(v));
}

// ---------------------------------------------------------------------------
// zero: vectorized grid-stride fill
// ---------------------------------------------------------------------------
__global__ void zero_kernel(float4* __restrict__ p, int n4) {
    for (int i = blockIdx.x * blockDim.x + threadIdx.x; i < n4;
         i += gridDim.x * blockDim.x)
        p[i] = make_float4(0.f, 0.f, 0.f, 0.f);
}

// ---------------------------------------------------------------------------
// GEMM: C[M,N] = f(A)[M,K] @ W[K,N]   (proven R7 config: 420us on GEMM2)
//   f(A) = relu(A + prev_bias[k]) when prev_bias != nullptr, else A.
// 128x64x16 tiles, 256 threads, 8x4 register microtile, packed f32x2 FMA.
// ---------------------------------------------------------------------------
__global__ __launch_bounds__(256) void gemm_kernel(
    const float* __restrict__ A, const float* __restrict__ pb,
    const float* __restrict__ W, float* __restrict__ C,
    int M, int K, int N)
{
    const int BM = 128, BN = 64, BK = 16;
    __shared__ float As[BK][BM];   // transposed (k-major)
    __shared__ float Bs[BK][BN];

    int tid = threadIdx.x;
    int tx = tid & 15;     // col group 0..15 (4 cols each)
    int ty = tid >> 4;     // row group 0..15 (8 rows each)
    int rowBase = blockIdx.x * BM;
    int colBase = blockIdx.y * BN;

    // acc[i2][j]: packed pair of rows (ty*8 + 2*i2, +1) x col (tx*4 + j)
    unsigned long long acc[4][4];
#pragma unroll
    for (int i = 0; i < 4; i++)
#pragma unroll
        for (int j = 0; j < 4; j++) acc[i][j] = 0ULL;

    for (int k0 = 0; k0 < K; k0 += BK) {
        // ---- load A tile: 128 rows x 16 k = 512 float4, 2 per thread ----
#pragma unroll
        for (int it = 0; it < 2; it++) {
            int idx = it * 256 + tid;
            int ar = idx >> 2;        // 0..127
            int aq = idx & 3;         // 0..3 (k-quad)
            int arow = rowBase + ar;
            int ak = k0 + aq * 4;
            float4 av = make_float4(0.f, 0.f, 0.f, 0.f);
            if (arow < M) {
                if (ak + 4 <= K) {
                    av = *(const float4*)(A + (size_t)arow * K + ak);
                    if (pb) {
                        av.x = fmaxf(av.x + __ldg(pb + ak + 0), 0.f);
                        av.y = fmaxf(av.y + __ldg(pb + ak + 1), 0.f);
                        av.z = fmaxf(av.z + __ldg(pb + ak + 2), 0.f);
                        av.w = fmaxf(av.w + __ldg(pb + ak + 3), 0.f);
                    }
                } else {
                    float t[4] = {0.f, 0.f, 0.f, 0.f};
#pragma unroll
                    for (int u = 0; u < 4; u++) {
                        if (ak + u < K) {
                            float v = A[(size_t)arow * K + ak + u];
                            if (pb) v = fmaxf(v + pb[ak + u], 0.f);
                            t[u] = v;
                        }
                    }
                    av = make_float4(t[0], t[1], t[2], t[3]);
                }
            }
            As[aq * 4 + 0][ar] = av.x;
            As[aq * 4 + 1][ar] = av.y;
            As[aq * 4 + 2][ar] = av.z;
            As[aq * 4 + 3][ar] = av.w;
        }

        // ---- load B tile: 16 k-rows x 64 cols = 256 float4, 1 per thread ----
        {
            int br = tid >> 4;        // 0..15 (k-row)
            int bq = tid & 15;        // 0..15 (float4 quad along N)
            int brow = k0 + br;
            int bcol = colBase + bq * 4;
            float4 bv = make_float4(0.f, 0.f, 0.f, 0.f);
            if (brow < K) {
                if (bcol + 4 <= N) {
                    bv = *(const float4*)(W + (size_t)brow * N + bcol);
                } else {
                    float t[4] = {0.f, 0.f, 0.f, 0.f};
#pragma unroll
                    for (int u = 0; u < 4; u++)
                        if (bcol + u < N) t[u] = W[(size_t)brow * N + bcol + u];
                    bv = make_float4(t[0], t[1], t[2], t[3]);
                }
            }
            *(float4*)&Bs[br][bq * 4] = bv;
        }

        __syncthreads();

#pragma unroll
        for (int k = 0; k < BK; k++) {
            float4 a0 = *(const float4*)&As[k][ty * 8];
            float4 a1 = *(const float4*)&As[k][ty * 8 + 4];
            float4 b  = *(const float4*)&Bs[k][tx * 4];

            unsigned long long ap[4];
            ap[0] = pk2(a0.x, a0.y);
            ap[1] = pk2(a0.z, a0.w);
            ap[2] = pk2(a1.x, a1.y);
            ap[3] = pk2(a1.z, a1.w);

            unsigned long long bp[4];
            bp[0] = pk2(b.x, b.x);
            bp[1] = pk2(b.y, b.y);
            bp[2] = pk2(b.z, b.z);
            bp[3] = pk2(b.w, b.w);

#pragma unroll
            for (int i2 = 0; i2 < 4; i2++)
#pragma unroll
                for (int j = 0; j < 4; j++)
                    fma2(acc[i2][j], ap[i2], bp[j]);
        }
        __syncthreads();
    }

    // ---- store ----
#pragma unroll
    for (int i2 = 0; i2 < 4; i2++) {
        int r0 = rowBase + ty * 8 + i2 * 2;
#pragma unroll
        for (int j = 0; j < 4; j++) {
            int col = colBase + tx * 4 + j;
            if (col >= N) continue;
            float lo, hi;
            unpk2(acc[i2][j], lo, hi);
            if (r0 < M)     C[(size_t)r0 * N + col] = lo;
            if (r0 + 1 < M) C[(size_t)(r0 + 1) * N + col] = hi;
        }
    }
}

// ---------------------------------------------------------------------------
// Warp-per-edge scatter (for large F): one broadcast edge-triple load per
// warp, lanes sweep feature chunks. Cuts edge-index traffic by F/4 x.
// ---------------------------------------------------------------------------
template <int F>
__global__ __launch_bounds__(256) void scatter_warp_kernel(
    const float* __restrict__ support,
    const int* __restrict__ src, const int* __restrict__ dst,
    const float* __restrict__ ew,
    float* __restrict__ agg, int E)
{
    constexpr int NCH = F / 4;
    int gw = (blockIdx.x * blockDim.x + threadIdx.x) >> 5;
    int lane = threadIdx.x & 31;
    if (gw >= E) return;

    int s = __ldg(src + gw);
    int d = __ldg(dst + gw);
    float w = __ldg(ew + gw);

    const float4* srow = (const float4*)(support + (size_t)s * F);
    float* drow = agg + (size_t)d * F;

#pragma unroll
    for (int c = lane; c < NCH; c += 32) {
        float4 v = __ldg(srow + c);
        v.x *= w; v.y *= w; v.z *= w; v.w *= w;
        float* out = drow + c * 4;
        asm volatile("red.global.add.v4.f32 [%0], {%1, %2, %3, %4};"
                     :: "l"(out), "f"(v.x), "f"(v.y), "f"(v.z), "f"(v.w)
                     : "memory");
    }
}

// ---------------------------------------------------------------------------
// Thread-per-(edge,chunk) scatter (for small F, keeps lanes busy)
// ---------------------------------------------------------------------------
template <int F>
__global__ __launch_bounds__(256) void scatter_kernel(
    const float* __restrict__ support,
    const int* __restrict__ src, const int* __restrict__ dst,
    const float* __restrict__ ew,
    float* __restrict__ agg, int E)
{
    constexpr int NCH = F / 4;
    int t = blockIdx.x * blockDim.x + threadIdx.x;
    if (t >= E * NCH) return;
    int e = t / NCH;
    int c = t - e * NCH;

    int s = __ldg(src + e);
    int d = __ldg(dst + e);
    float w = __ldg(ew + e);

    float4 v = __ldg((const float4*)(support + (size_t)s * F) + c);
    v.x *= w; v.y *= w; v.z *= w; v.w *= w;

    float* out = agg + (size_t)d * F + c * 4;
    asm volatile("red.global.add.v4.f32 [%0], {%1, %2, %3, %4};"
                 :: "l"(out), "f"(v.x), "f"(v.y), "f"(v.z), "f"(v.w)
                 : "memory");
}

// ---------------------------------------------------------------------------
// Softmax over 40 classes; one warp per node. input = agg + b3.
// ---------------------------------------------------------------------------
__global__ __launch_bounds__(256) void softmax_kernel(
    const float* __restrict__ agg, const float* __restrict__ b,
    float* __restrict__ out, int M)
{
    int warp = (blockIdx.x * blockDim.x + threadIdx.x) >> 5;
    int lane = threadIdx.x & 31;
    if (warp >= M) return;

    const float* row = agg + (size_t)warp * 40;
    float v0 = row[lane] + __ldg(b + lane);
    float v1 = (lane < 8) ? row[32 + lane] + __ldg(b + 32 + lane) : -3.4e38f;

    float m = fmaxf(v0, v1);
#pragma unroll
    for (int o = 16; o > 0; o >>= 1) m = fmaxf(m, __shfl_xor_sync(0xFFFFFFFFu, m, o));

    float e0 = __expf(v0 - m);
    float e1 = (lane < 8) ? __expf(v1 - m) : 0.f;
    float s = e0 + e1;
#pragma unroll
    for (int o = 16; o > 0; o >>= 1) s += __shfl_xor_sync(0xFFFFFFFFu, s, o);

    float inv = 1.f / s;
    float* orow = out + (size_t)warp * 40;
    orow[lane] = e0 * inv;
    if (lane < 8) orow[32 + lane] = e1 * inv;
}

// ---------------------------------------------------------------------------
// launch
// ---------------------------------------------------------------------------
extern "C" void kernel_launch(void* const* d_in, const int* in_sizes, int n_in,
                              void* d_out, int out_size)
{
    const float* x  = (const float*)d_in[0];
    const int*   ei = (const int*)d_in[1];
    const float* ew = (const float*)d_in[2];
    const float* w1 = (const float*)d_in[3];
    const float* b1 = (const float*)d_in[4];
    const float* w2 = (const float*)d_in[5];
    const float* b2 = (const float*)d_in[6];
    const float* w3 = (const float*)d_in[7];
    const float* b3 = (const float*)d_in[8];
    float* out = (float*)d_out;

    const int M = NNODES;
    const int E = in_sizes[2];
    const int* src = ei;
    const int* dst = ei + E;

    float *support, *agg;
    cudaGetSymbolAddress((void**)&support, g_support);
    cudaGetSymbolAddress((void**)&agg, g_agg);

    const int warpsPerBlock = 256 / 32;
    unsigned scatterBlocks = (unsigned)((E + warpsPerBlock - 1) / warpsPerBlock);

    // ---- Layer 1: support = x @ w1 ; agg = A @ support ----
    {
        const int K = 512, N = 300;
        dim3 grid((M + 127) / 128, (N + 63) / 64);
        gemm_kernel<<<grid, 256>>>(x, nullptr, w1, support, M, K, N);
        int n4 = M * N / 4;
        zero_kernel<<<2048, 256>>>((float4*)agg, n4);
        scatter_warp_kernel<300><<<scatterBlocks, 256>>>(
            support, src, dst, ew, agg, E);
    }
    // ---- Layer 2: support = relu(agg + b1) @ w2 ; agg = A @ support ----
    {
        const int K = 300, N = 200;
        dim3 grid((M + 127) / 128, (N + 63) / 64);
        gemm_kernel<<<grid, 256>>>(agg, b1, w2, support, M, K, N);
        int n4 = M * N / 4;
        zero_kernel<<<2048, 256>>>((float4*)agg, n4);
        scatter_warp_kernel<200><<<scatterBlocks, 256>>>(
            support, src, dst, ew, agg, E);
    }
    // ---- Layer 3: support = relu(agg + b2) @ w3 ; agg = A @ support ----
    {
        const int K = 200, N = 40;
        dim3 grid((M + 127) / 128, (N + 63) / 64);
        gemm_kernel<<<grid, 256>>>(agg, b2, w3, support, M, K, N);
        int n4 = M * N / 4;
        zero_kernel<<<1024, 256>>>((float4*)agg, n4);
        long long tot = (long long)E * (40 / 4);
        scatter_kernel<40><<<(unsigned)((tot + 255) / 256), 256>>>(
            support, src, dst, ew, agg, E);
    }
    // ---- softmax(agg + b3) -> out ----
    {
        int grid = (M + warpsPerBlock - 1) / warpsPerBlock;
        softmax_kernel<<<grid, 256>>>(agg, b3, out, M);
    }
}

// round 16
// speedup vs baseline: 1.9067x; 1.5496x over previous
#include <cuda_runtime.h>
#include <cstdint>

#define NNODES 100000
#define EMAX   3200000
#define MAXF   300

// Scratch (static __device__ arrays: allocation-guard compliant)
__device__ float g_support[(size_t)NNODES * MAXF];
__device__ float g_agg[(size_t)NNODES * MAXF];
__device__ int   g_offsets[NNODES + 1];   // counts -> exclusive offsets (in place)
__device__ int   g_cursor[NNODES];
__device__ int   g_csr_src[EMAX];
__device__ float g_csr_w[EMAX];

// ---------------------------------------------------------------------------
// packed fp32x2 helpers (Blackwell: fma.rn.f32x2 doubles fp32 FMA throughput)
// ---------------------------------------------------------------------------
__device__ __forceinline__ unsigned long long pk2(float lo, float hi) {
    unsigned long long r;
    asm("mov.b64 %0, {%1, %2};" : "=l"(r) : "f"(lo), "f"(hi));
    return r;
}
__device__ __forceinline__ void fma2(unsigned long long& d,
                                     unsigned long long a,
                                     unsigned long long b) {
    asm("fma.rn.f32x2 %0, %1, %2, %0;" : "+l"(d) : "l"(a), "l"(b));
}
__device__ __forceinline__ void unpk2(unsigned long long v, float& lo, float& hi) {
    asm("mov.b64 {%0, %1}, %2;" : "=f"(lo), "=f"(hi) : "l"(v));
}

// ---------------------------------------------------------------------------
// CSR build: zero counts -> histogram -> scan -> bucket place
// ---------------------------------------------------------------------------
__global__ void zero_int_kernel(int* __restrict__ p, int n) {
    for (int i = blockIdx.x * blockDim.x + threadIdx.x; i < n;
         i += gridDim.x * blockDim.x)
        p[i] = 0;
}

__global__ void hist_kernel(const int* __restrict__ dst, int E,
                            int* __restrict__ counts) {
    int t = blockIdx.x * blockDim.x + threadIdx.x;
    if (t < E) atomicAdd(&counts[__ldg(dst + t)], 1);
}

// Single-block exclusive scan over NNODES counts (in place), also fills cursor.
__global__ void scan_kernel(int* __restrict__ counts, int* __restrict__ cursor,
                            int n) {
    const int T = 1024;
    __shared__ int partial[T];
    int t = threadIdx.x;
    int C = (n + T - 1) / T;
    int lo = t * C, hi = min(lo + C, n);

    int sum = 0;
    for (int i = lo; i < hi; i++) sum += counts[i];
    partial[t] = sum;
    __syncthreads();

    // Kogge-Stone inclusive scan
    for (int off = 1; off < T; off <<= 1) {
        int v = (t >= off) ? partial[t - off] : 0;
        __syncthreads();
        partial[t] += v;
        __syncthreads();
    }
    int base = partial[t] - sum;   // exclusive prefix for this segment
    int total = partial[T - 1];

    int run = base;
    for (int i = lo; i < hi; i++) {
        int c = counts[i];
        counts[i] = run;
        cursor[i] = run;
        run += c;
    }
    if (t == T - 1) counts[n] = total;
}

__global__ void build_kernel(const int* __restrict__ src,
                             const int* __restrict__ dst,
                             const float* __restrict__ ew, int E,
                             int* __restrict__ cursor,
                             int* __restrict__ csr_src,
                             float* __restrict__ csr_w) {
    int t = blockIdx.x * blockDim.x + threadIdx.x;
    if (t >= E) return;
    int d = __ldg(dst + t);
    int p = atomicAdd(&cursor[d], 1);
    csr_src[p] = __ldg(src + t);
    csr_w[p] = __ldg(ew + t);
}

// ---------------------------------------------------------------------------
// GEMM: C[M,N] = f(A)[M,K] @ W[K,N]   (proven R7 config: 420us on GEMM2)
//   f(A) = relu(A + prev_bias[k]) when prev_bias != nullptr, else A.
// 128x64x16 tiles, 256 threads, 8x4 register microtile, packed f32x2 FMA.
// ---------------------------------------------------------------------------
__global__ __launch_bounds__(256) void gemm_kernel(
    const float* __restrict__ A, const float* __restrict__ pb,
    const float* __restrict__ W, float* __restrict__ C,
    int M, int K, int N)
{
    const int BM = 128, BN = 64, BK = 16;
    __shared__ float As[BK][BM];   // transposed (k-major)
    __shared__ float Bs[BK][BN];

    int tid = threadIdx.x;
    int tx = tid & 15;     // col group 0..15 (4 cols each)
    int ty = tid >> 4;     // row group 0..15 (8 rows each)
    int rowBase = blockIdx.x * BM;
    int colBase = blockIdx.y * BN;

    unsigned long long acc[4][4];
#pragma unroll
    for (int i = 0; i < 4; i++)
#pragma unroll
        for (int j = 0; j < 4; j++) acc[i][j] = 0ULL;

    for (int k0 = 0; k0 < K; k0 += BK) {
        // ---- load A tile: 128 rows x 16 k = 512 float4, 2 per thread ----
#pragma unroll
        for (int it = 0; it < 2; it++) {
            int idx = it * 256 + tid;
            int ar = idx >> 2;        // 0..127
            int aq = idx & 3;         // 0..3 (k-quad)
            int arow = rowBase + ar;
            int ak = k0 + aq * 4;
            float4 av = make_float4(0.f, 0.f, 0.f, 0.f);
            if (arow < M) {
                if (ak + 4 <= K) {
                    av = *(const float4*)(A + (size_t)arow * K + ak);
                    if (pb) {
                        av.x = fmaxf(av.x + __ldg(pb + ak + 0), 0.f);
                        av.y = fmaxf(av.y + __ldg(pb + ak + 1), 0.f);
                        av.z = fmaxf(av.z + __ldg(pb + ak + 2), 0.f);
                        av.w = fmaxf(av.w + __ldg(pb + ak + 3), 0.f);
                    }
                } else {
                    float t[4] = {0.f, 0.f, 0.f, 0.f};
#pragma unroll
                    for (int u = 0; u < 4; u++) {
                        if (ak + u < K) {
                            float v = A[(size_t)arow * K + ak + u];
                            if (pb) v = fmaxf(v + pb[ak + u], 0.f);
                            t[u] = v;
                        }
                    }
                    av = make_float4(t[0], t[1], t[2], t[3]);
                }
            }
            As[aq * 4 + 0][ar] = av.x;
            As[aq * 4 + 1][ar] = av.y;
            As[aq * 4 + 2][ar] = av.z;
            As[aq * 4 + 3][ar] = av.w;
        }

        // ---- load B tile: 16 k-rows x 64 cols = 256 float4, 1 per thread ----
        {
            int br = tid >> 4;        // 0..15 (k-row)
            int bq = tid & 15;        // 0..15 (float4 quad along N)
            int brow = k0 + br;
            int bcol = colBase + bq * 4;
            float4 bv = make_float4(0.f, 0.f, 0.f, 0.f);
            if (brow < K) {
                if (bcol + 4 <= N) {
                    bv = *(const float4*)(W + (size_t)brow * N + bcol);
                } else {
                    float t[4] = {0.f, 0.f, 0.f, 0.f};
#pragma unroll
                    for (int u = 0; u < 4; u++)
                        if (bcol + u < N) t[u] = W[(size_t)brow * N + bcol + u];
                    bv = make_float4(t[0], t[1], t[2], t[3]);
                }
            }
            *(float4*)&Bs[br][bq * 4] = bv;
        }

        __syncthreads();

#pragma unroll
        for (int k = 0; k < BK; k++) {
            float4 a0 = *(const float4*)&As[k][ty * 8];
            float4 a1 = *(const float4*)&As[k][ty * 8 + 4];
            float4 b  = *(const float4*)&Bs[k][tx * 4];

            unsigned long long ap[4];
            ap[0] = pk2(a0.x, a0.y);
            ap[1] = pk2(a0.z, a0.w);
            ap[2] = pk2(a1.x, a1.y);
            ap[3] = pk2(a1.z, a1.w);

            unsigned long long bp[4];
            bp[0] = pk2(b.x, b.x);
            bp[1] = pk2(b.y, b.y);
            bp[2] = pk2(b.z, b.z);
            bp[3] = pk2(b.w, b.w);

#pragma unroll
            for (int i2 = 0; i2 < 4; i2++)
#pragma unroll
                for (int j = 0; j < 4; j++)
                    fma2(acc[i2][j], ap[i2], bp[j]);
        }
        __syncthreads();
    }

    // ---- store ----
#pragma unroll
    for (int i2 = 0; i2 < 4; i2++) {
        int r0 = rowBase + ty * 8 + i2 * 2;
#pragma unroll
        for (int j = 0; j < 4; j++) {
            int col = colBase + tx * 4 + j;
            if (col >= N) continue;
            float lo, hi;
            unpk2(acc[i2][j], lo, hi);
            if (r0 < M)     C[(size_t)r0 * N + col] = lo;
            if (r0 + 1 < M) C[(size_t)(r0 + 1) * N + col] = hi;
        }
    }
}

// ---------------------------------------------------------------------------
// Gather aggregation: warp per node, register accumulation, single write.
// agg[n] = sum_{e in in(n)} support[csr_src[e]] * csr_w[e]
// ---------------------------------------------------------------------------
template <int F>
__global__ __launch_bounds__(256) void gather_kernel(
    const float* __restrict__ support,
    const int* __restrict__ csr_src, const float* __restrict__ csr_w,
    const int* __restrict__ offsets,
    float* __restrict__ agg, int Mnodes)
{
    constexpr int NCH = F / 4;
    constexpr int R = (NCH + 31) / 32;
    int node = (blockIdx.x * blockDim.x + threadIdx.x) >> 5;
    int lane = threadIdx.x & 31;
    if (node >= Mnodes) return;

    int beg = __ldg(offsets + node);
    int end = __ldg(offsets + node + 1);

    float4 acc[R];
#pragma unroll
    for (int r = 0; r < R; r++) acc[r] = make_float4(0.f, 0.f, 0.f, 0.f);

    for (int i = beg; i < end; i++) {
        int s = __ldg(csr_src + i);
        float w = __ldg(csr_w + i);
        const float4* srow = (const float4*)(support + (size_t)s * F);
#pragma unroll
        for (int r = 0; r < R; r++) {
            int c = lane + 32 * r;
            if (c < NCH) {
                float4 v = __ldg(srow + c);
                acc[r].x = fmaf(v.x, w, acc[r].x);
                acc[r].y = fmaf(v.y, w, acc[r].y);
                acc[r].z = fmaf(v.z, w, acc[r].z);
                acc[r].w = fmaf(v.w, w, acc[r].w);
            }
        }
    }

    float4* drow = (float4*)(agg + (size_t)node * F);
#pragma unroll
    for (int r = 0; r < R; r++) {
        int c = lane + 32 * r;
        if (c < NCH) drow[c] = acc[r];
    }
}

// ---------------------------------------------------------------------------
// Softmax over 40 classes; one warp per node. input = agg + b3.
// ---------------------------------------------------------------------------
__global__ __launch_bounds__(256) void softmax_kernel(
    const float* __restrict__ agg, const float* __restrict__ b,
    float* __restrict__ out, int M)
{
    int warp = (blockIdx.x * blockDim.x + threadIdx.x) >> 5;
    int lane = threadIdx.x & 31;
    if (warp >= M) return;

    const float* row = agg + (size_t)warp * 40;
    float v0 = row[lane] + __ldg(b + lane);
    float v1 = (lane < 8) ? row[32 + lane] + __ldg(b + 32 + lane) : -3.4e38f;

    float m = fmaxf(v0, v1);
#pragma unroll
    for (int o = 16; o > 0; o >>= 1) m = fmaxf(m, __shfl_xor_sync(0xFFFFFFFFu, m, o));

    float e0 = __expf(v0 - m);
    float e1 = (lane < 8) ? __expf(v1 - m) : 0.f;
    float s = e0 + e1;
#pragma unroll
    for (int o = 16; o > 0; o >>= 1) s += __shfl_xor_sync(0xFFFFFFFFu, s, o);

    float inv = 1.f / s;
    float* orow = out + (size_t)warp * 40;
    orow[lane] = e0 * inv;
    if (lane < 8) orow[32 + lane] = e1 * inv;
}

// ---------------------------------------------------------------------------
// launch
// ---------------------------------------------------------------------------
extern "C" void kernel_launch(void* const* d_in, const int* in_sizes, int n_in,
                              void* d_out, int out_size)
{
    const float* x  = (const float*)d_in[0];
    const int*   ei = (const int*)d_in[1];
    const float* ew = (const float*)d_in[2];
    const float* w1 = (const float*)d_in[3];
    const float* b1 = (const float*)d_in[4];
    const float* w2 = (const float*)d_in[5];
    const float* b2 = (const float*)d_in[6];
    const float* w3 = (const float*)d_in[7];
    const float* b3 = (const float*)d_in[8];
    float* out = (float*)d_out;

    const int M = NNODES;
    const int E = in_sizes[2];
    const int* src = ei;
    const int* dst = ei + E;

    float *support, *agg, *csr_w;
    int *offsets, *cursor, *csr_src;
    cudaGetSymbolAddress((void**)&support, g_support);
    cudaGetSymbolAddress((void**)&agg, g_agg);
    cudaGetSymbolAddress((void**)&offsets, g_offsets);
    cudaGetSymbolAddress((void**)&cursor, g_cursor);
    cudaGetSymbolAddress((void**)&csr_src, g_csr_src);
    cudaGetSymbolAddress((void**)&csr_w, g_csr_w);

    const int warpsPerBlock = 256 / 32;
    unsigned nodeBlocks = (unsigned)((M + warpsPerBlock - 1) / warpsPerBlock);
    unsigned edgeBlocks = (unsigned)((E + 255) / 256);

    // ---- Build CSR (dst-sorted edges) once per launch ----
    zero_int_kernel<<<256, 256>>>(offsets, M + 1);
    hist_kernel<<<edgeBlocks, 256>>>(dst, E, offsets);
    scan_kernel<<<1, 1024>>>(offsets, cursor, M);
    build_kernel<<<edgeBlocks, 256>>>(src, dst, ew, E, cursor, csr_src, csr_w);

    // ---- Layer 1: support = x @ w1 ; agg = A @ support ----
    {
        const int K = 512, N = 300;
        dim3 grid((M + 127) / 128, (N + 63) / 64);
        gemm_kernel<<<grid, 256>>>(x, nullptr, w1, support, M, K, N);
        gather_kernel<300><<<nodeBlocks, 256>>>(support, csr_src, csr_w,
                                                offsets, agg, M);
    }
    // ---- Layer 2: support = relu(agg + b1) @ w2 ; agg = A @ support ----
    {
        const int K = 300, N = 200;
        dim3 grid((M + 127) / 128, (N + 63) / 64);
        gemm_kernel<<<grid, 256>>>(agg, b1, w2, support, M, K, N);
        gather_kernel<200><<<nodeBlocks, 256>>>(support, csr_src, csr_w,
                                                offsets, agg, M);
    }
    // ---- Layer 3: support = relu(agg + b2) @ w3 ; agg = A @ support ----
    {
        const int K = 200, N = 40;
        dim3 grid((M + 127) / 128, (N + 63) / 64);
        gemm_kernel<<<grid, 256>>>(agg, b2, w3, support, M, K, N);
        gather_kernel<40><<<nodeBlocks, 256>>>(support, csr_src, csr_w,
                                               offsets, agg, M);
    }
    // ---- softmax(agg + b3) -> out ----
    {
        int grid = (M + warpsPerBlock - 1) / warpsPerBlock;
        softmax_kernel<<<grid, 256>>>(agg, b3, out, M);
    }
}